// round 7
// baseline (speedup 1.0000x reference)
#include <cuda_runtime.h>

// Problem constants
#define CCH     12            // path channels: 1 time + 3 orig + 8 aug
#define TT      1024
#define NCHUNK  16
#define CHLEN   64            // chunk 15 has 63 steps (16*64-1 = 1023)
#define NPATH   64            // B(32) * GROUPS(2)
#define SIGC    1884          // 12 + 144 + 1728
#define L2OFF   12
#define L3OFF   156
#define TSTRIDE 68            // padded t-stride of transposed dx (float4-aligned)
#define SIGQ    471           // SIGC / 4 float4s

// Scratch (no cudaMalloc allowed)
__device__ __align__(16) float g_part[NPATH * NCHUNK * SIGC]; // ~7.7 MB
__device__ __align__(16) float g_sig [NPATH * SIGC];          // ~0.5 MB

// ---------------------------------------------------------------------------
// Chen fold body: A = A (x) B (truncated, depth 3), thread owns (i,j,kg).
// ---------------------------------------------------------------------------
__device__ __forceinline__ void chen_fold(const float* __restrict__ bp,
        int i, int j, int t144, int kg,
        float4& A3, float& A2ij, float& a1i)
{
    const float4 u4  = *(const float4*)(bp + kg * 4);                     // B1 quad
    const float  b1i = bp[i];
    const float  b1j = bp[j];
    const float4 q   = *(const float4*)(bp + L2OFF + j * 12 + kg * 4);    // B2[j] quad
    const float  b2  = bp[L2OFF + i * CCH + j];
    const float4 r   = *(const float4*)(bp + L3OFF + t144 * 12 + kg * 4); // B3 quad

    // old A1, old A2
    A3.x += r.x; A3.x = fmaf(a1i, q.x, A3.x); A3.x = fmaf(A2ij, u4.x, A3.x);
    A3.y += r.y; A3.y = fmaf(a1i, q.y, A3.y); A3.y = fmaf(A2ij, u4.y, A3.y);
    A3.z += r.z; A3.z = fmaf(a1i, q.z, A3.z); A3.z = fmaf(A2ij, u4.z, A3.z);
    A3.w += r.w; A3.w = fmaf(a1i, q.w, A3.w); A3.w = fmaf(A2ij, u4.w, A3.w);
    A2ij += b2 + a1i * b1j;   // old A1
    a1i  += b1i;
}

// ---------------------------------------------------------------------------
// Kernel 1: per-chunk partial signature (unchanged — known ~17us warm).
// grid = (NCHUNK, NPATH) = 1024 blocks, block = 160 (144 active).
// ---------------------------------------------------------------------------
__global__ __launch_bounds__(160) void chunk_kernel(const float* __restrict__ x,
                                                    const float* __restrict__ aug_w)
{
    __shared__ __align__(16) float dxsh[CHLEN * CCH];       // [t][c]
    __shared__ __align__(16) float dxT [CCH * TSTRIDE];     // [c][t_padded]
    __shared__ float xsh[(CHLEN + 1) * 3];
    __shared__ float awsh[8 * 3];

    const int tid   = threadIdx.x;
    const int chunk = blockIdx.x;
    const int p     = blockIdx.y;        // path id = b*2 + g
    const int b     = p >> 1;
    const int g     = p & 1;
    const int t0    = chunk * CHLEN;
    const int ns    = (chunk == NCHUNK - 1) ? (CHLEN - 1) : CHLEN;   // steps

    for (int idx = tid; idx < (ns + 1) * 3; idx += blockDim.x)
        xsh[idx] = x[(b * TT + t0) * 3 + idx];
    if (tid < 24) awsh[tid] = aug_w[g * 24 + tid];
    __syncthreads();

    for (int idx = tid; idx < ns * CCH; idx += blockDim.x) {
        int t = idx / CCH, c = idx - t * CCH;
        float xd0 = xsh[(t + 1) * 3 + 0] - xsh[t * 3 + 0];
        float xd1 = xsh[(t + 1) * 3 + 1] - xsh[t * 3 + 1];
        float xd2 = xsh[(t + 1) * 3 + 2] - xsh[t * 3 + 2];
        float v;
        if (c == 0)      v = 1.0f / 1023.0f;
        else if (c == 1) v = xd0;
        else if (c == 2) v = xd1;
        else if (c == 3) v = xd2;
        else {
            int e = c - 4;
            v = fmaf(awsh[e * 3 + 0], xd0,
                fmaf(awsh[e * 3 + 1], xd1,
                     awsh[e * 3 + 2] * xd2));
        }
        dxsh[idx] = v;
        dxT[c * TSTRIDE + t] = v;
    }
    __syncthreads();

    if (tid < 144) {
        const int i = tid / CCH, j = tid - CCH * (tid / CCH);
        float S3[12];
#pragma unroll
        for (int k = 0; k < 12; k++) S3[k] = 0.0f;
        float S2 = 0.0f;
        float s1 = 0.0f;
        const float4* __restrict__ dxq = (const float4*)dxsh;
        const float4* __restrict__ diT = (const float4*)(dxT + i * TSTRIDE);
        const float4* __restrict__ djT = (const float4*)(dxT + j * TSTRIDE);

#define SIG_STEP(tq, di_, dj_) {                                              \
        const float4 d0 = dxq[(tq) * 3 + 0];                                  \
        const float4 d1 = dxq[(tq) * 3 + 1];                                  \
        const float4 d2 = dxq[(tq) * 3 + 2];                                  \
        const float cc = fmaf(fmaf((di_), 1.0f/6.0f, 0.5f * s1), (dj_), S2);  \
        S3[0]  = fmaf(cc, d0.x, S3[0]);                                       \
        S3[1]  = fmaf(cc, d0.y, S3[1]);                                       \
        S3[2]  = fmaf(cc, d0.z, S3[2]);                                       \
        S3[3]  = fmaf(cc, d0.w, S3[3]);                                       \
        S3[4]  = fmaf(cc, d1.x, S3[4]);                                       \
        S3[5]  = fmaf(cc, d1.y, S3[5]);                                       \
        S3[6]  = fmaf(cc, d1.z, S3[6]);                                       \
        S3[7]  = fmaf(cc, d1.w, S3[7]);                                       \
        S3[8]  = fmaf(cc, d2.x, S3[8]);                                       \
        S3[9]  = fmaf(cc, d2.y, S3[9]);                                       \
        S3[10] = fmaf(cc, d2.z, S3[10]);                                      \
        S3[11] = fmaf(cc, d2.w, S3[11]);                                      \
        S2 = fmaf(fmaf((di_), 0.5f, s1), (dj_), S2);                          \
        s1 += (di_); }

        const int nq = ns >> 2;           // full quads of steps
#pragma unroll 4
        for (int tb = 0; tb < nq; tb++) {
            const float4 di4 = diT[tb];
            const float4 dj4 = djT[tb];
            SIG_STEP(tb * 4 + 0, di4.x, dj4.x);
            SIG_STEP(tb * 4 + 1, di4.y, dj4.y);
            SIG_STEP(tb * 4 + 2, di4.z, dj4.z);
            SIG_STEP(tb * 4 + 3, di4.w, dj4.w);
        }
        for (int t = nq * 4; t < ns; t++) {   // remainder (0 or 3 steps)
            const float di = dxT[i * TSTRIDE + t];
            const float dj = dxT[j * TSTRIDE + t];
            SIG_STEP(t, di, dj);
        }
#undef SIG_STEP

        float* out = &g_part[(size_t)(p * NCHUNK + chunk) * SIGC];
        if (j == 0) out[i] = s1;
        out[L2OFF + tid] = S2;
        float4* o4 = (float4*)(out + L3OFF + tid * 12);
        o4[0] = make_float4(S3[0], S3[1], S3[2],  S3[3]);
        o4[1] = make_float4(S3[4], S3[5], S3[6],  S3[7]);
        o4[2] = make_float4(S3[8], S3[9], S3[10], S3[11]);
    }
}

// ---------------------------------------------------------------------------
// Kernel 2: per-path combine. grid = 64 (one block per path), block = 512.
// Bulk-stage ALL 16 chunk partials (120.5 KB) into dynamic smem in one burst
// (14.7 independent LDG.128 per thread -> deep MLP), then 15 folds entirely
// from smem, write final signature to g_sig.
// ---------------------------------------------------------------------------
extern __shared__ float dynsh[];

__global__ __launch_bounds__(512) void combine_kernel()
{
    const int tid = threadIdx.x;
    const int p   = blockIdx.x;

    const float4* __restrict__ gsrc =
        (const float4*)&g_part[(size_t)p * NCHUNK * SIGC];
    const int NQ = NCHUNK * SIGQ;   // 7536 float4s
    for (int f = tid; f < NQ; f += 512)
        ((float4*)dynsh)[f] = gsrc[f];
    __syncthreads();

    if (tid < 432) {
        const int t144 = tid / 3;
        const int kg   = tid - 3 * t144;
        const int i    = t144 / CCH;
        const int j    = t144 - CCH * i;

        float4 A3   = *(const float4*)(dynsh + L3OFF + t144 * 12 + kg * 4);
        float  A2ij = dynsh[L2OFF + t144];
        float  a1i  = dynsh[i];

#pragma unroll
        for (int s = 1; s < NCHUNK; s++)
            chen_fold(dynsh + s * SIGC, i, j, t144, kg, A3, A2ij, a1i);

        float* out = &g_sig[(size_t)p * SIGC];
        *(float4*)(out + L3OFF + t144 * 12 + kg * 4) = A3;
        if (kg == 0) {
            out[L2OFF + t144] = A2ij;
            if (j == 0) out[i] = a1i;
        }
    }
}

// ---------------------------------------------------------------------------
// Kernel 3: GEMV + sigmoid. grid = 32 (batch), block = 1024.
// Stage the batch's contiguous sig pair (15 KB) into smem, then warp o
// computes out[b][o] with float4 loads + shuffle reduction.
// ---------------------------------------------------------------------------
__global__ __launch_bounds__(1024) void linear_kernel(const float* __restrict__ lin_w,
                                                      const float* __restrict__ lin_b,
                                                      float* __restrict__ out)
{
    __shared__ __align__(16) float sig[2 * SIGC];   // 15 KB

    const int tid = threadIdx.x;
    const int b   = blockIdx.x;

    const float4* __restrict__ gsig =
        (const float4*)&g_sig[(size_t)(2 * b) * SIGC];
    const int NV = (2 * SIGC) / 4;   // 942
    for (int f = tid; f < NV; f += 1024)
        ((float4*)sig)[f] = gsig[f];
    __syncthreads();

    const int o    = tid >> 5;
    const int lane = tid & 31;
    const float4* __restrict__ s4 = (const float4*)sig;
    const float4* __restrict__ w4 = (const float4*)(lin_w + (size_t)o * 2 * SIGC);

    float ax = 0.0f, ay = 0.0f, az = 0.0f, aw = 0.0f;
    for (int f = lane; f < NV; f += 32) {
        float4 sv = s4[f];
        float4 wv = w4[f];
        ax = fmaf(sv.x, wv.x, ax);
        ay = fmaf(sv.y, wv.y, ay);
        az = fmaf(sv.z, wv.z, az);
        aw = fmaf(sv.w, wv.w, aw);
    }
    float acc = (ax + ay) + (az + aw);
#pragma unroll
    for (int off = 16; off > 0; off >>= 1)
        acc += __shfl_down_sync(0xffffffffu, acc, off);
    if (lane == 0) {
        float z = acc + lin_b[o];
        out[b * 32 + o] = 1.0f / (1.0f + expf(-z));
    }
}

// ---------------------------------------------------------------------------
extern "C" void kernel_launch(void* const* d_in, const int* in_sizes, int n_in,
                              void* d_out, int out_size)
{
    const float* x     = (const float*)d_in[0];  // (32,1024,3)
    const float* aug_w = (const float*)d_in[1];  // (2,8,3)
    // d_in[2] = aug_b : unused (signature is translation-invariant)
    const float* lin_w = (const float*)d_in[3];  // (32, 3768)
    const float* lin_b = (const float*)d_in[4];  // (32,)
    float* out = (float*)d_out;                  // (32,32) float32

    const int dyn_smem = NCHUNK * SIGC * (int)sizeof(float);   // 120,576 B
    cudaFuncSetAttribute(combine_kernel,
                         cudaFuncAttributeMaxDynamicSharedMemorySize, dyn_smem);

    dim3 grid1(NCHUNK, NPATH);
    chunk_kernel<<<grid1, 160>>>(x, aug_w);
    combine_kernel<<<NPATH, 512, dyn_smem>>>();
    linear_kernel<<<32, 1024>>>(lin_w, lin_b, out);
}

// round 8
// speedup vs baseline: 1.0605x; 1.0605x over previous
#include <cuda_runtime.h>

// Problem constants
#define CCH     12            // path channels: 1 time + 3 orig + 8 aug
#define TT      1024
#define NCHUNK  8
#define CHLEN   128           // chunk 7 has 127 steps (8*128-1 = 1023)
#define NPATH   64            // B(32) * GROUPS(2)
#define SIGC    1884          // 12 + 144 + 1728
#define L2OFF   12
#define L3OFF   156
#define TSTRIDE 132           // padded t-stride of transposed dx (float4-aligned)
#define SIGQ    471           // SIGC / 4 float4s

// Scratch (no cudaMalloc allowed)
__device__ __align__(16) float g_part[NPATH * NCHUNK * SIGC]; // ~3.9 MB
__device__ __align__(16) float g_sig [NPATH * SIGC];          // ~0.5 MB

// ---------------------------------------------------------------------------
// Chen fold body: A = A (x) B (truncated, depth 3), thread owns (i,j,kg).
// ---------------------------------------------------------------------------
__device__ __forceinline__ void chen_fold(const float* __restrict__ bp,
        int i, int j, int t144, int kg,
        float4& A3, float& A2ij, float& a1i)
{
    const float4 u4  = *(const float4*)(bp + kg * 4);                     // B1 quad
    const float  b1i = bp[i];
    const float  b1j = bp[j];
    const float4 q   = *(const float4*)(bp + L2OFF + j * 12 + kg * 4);    // B2[j] quad
    const float  b2  = bp[L2OFF + i * CCH + j];
    const float4 r   = *(const float4*)(bp + L3OFF + t144 * 12 + kg * 4); // B3 quad

    // old A1, old A2
    A3.x += r.x; A3.x = fmaf(a1i, q.x, A3.x); A3.x = fmaf(A2ij, u4.x, A3.x);
    A3.y += r.y; A3.y = fmaf(a1i, q.y, A3.y); A3.y = fmaf(A2ij, u4.y, A3.y);
    A3.z += r.z; A3.z = fmaf(a1i, q.z, A3.z); A3.z = fmaf(A2ij, u4.z, A3.z);
    A3.w += r.w; A3.w = fmaf(a1i, q.w, A3.w); A3.w = fmaf(A2ij, u4.w, A3.w);
    A2ij += b2 + a1i * b1j;   // old A1
    a1i  += b1i;
}

// ---------------------------------------------------------------------------
// Kernel 1: per-chunk partial signature, f32x2-packed S3 accumulators.
// grid = (NCHUNK, NPATH) = 512 blocks, block = 160 (144 active).
// Thread (i,j): S3 as 6 packed f32x2 pairs (fma.rn.f32x2), S2 + S1 scalar.
// dx in two layouts: [t][c] (read as ulonglong2 pairs) and transposed [c][t].
// ---------------------------------------------------------------------------
__global__ __launch_bounds__(160) void chunk_kernel(const float* __restrict__ x,
                                                    const float* __restrict__ aug_w)
{
    __shared__ __align__(16) float dxsh[CHLEN * CCH];       // [t][c], 6 KB
    __shared__ __align__(16) float dxT [CCH * TSTRIDE];     // [c][t_padded]
    __shared__ float xsh[(CHLEN + 1) * 3];
    __shared__ float awsh[8 * 3];

    const int tid   = threadIdx.x;
    const int chunk = blockIdx.x;
    const int p     = blockIdx.y;        // path id = b*2 + g
    const int b     = p >> 1;
    const int g     = p & 1;
    const int t0    = chunk * CHLEN;
    const int ns    = (chunk == NCHUNK - 1) ? (CHLEN - 1) : CHLEN;   // steps

    for (int idx = tid; idx < (ns + 1) * 3; idx += blockDim.x)
        xsh[idx] = x[(b * TT + t0) * 3 + idx];
    if (tid < 24) awsh[tid] = aug_w[g * 24 + tid];
    __syncthreads();

    for (int idx = tid; idx < ns * CCH; idx += blockDim.x) {
        int t = idx / CCH, c = idx - t * CCH;
        float xd0 = xsh[(t + 1) * 3 + 0] - xsh[t * 3 + 0];
        float xd1 = xsh[(t + 1) * 3 + 1] - xsh[t * 3 + 1];
        float xd2 = xsh[(t + 1) * 3 + 2] - xsh[t * 3 + 2];
        float v;
        if (c == 0)      v = 1.0f / 1023.0f;
        else if (c == 1) v = xd0;
        else if (c == 2) v = xd1;
        else if (c == 3) v = xd2;
        else {
            int e = c - 4;
            v = fmaf(awsh[e * 3 + 0], xd0,
                fmaf(awsh[e * 3 + 1], xd1,
                     awsh[e * 3 + 2] * xd2));
        }
        dxsh[idx] = v;
        dxT[c * TSTRIDE + t] = v;
    }
    __syncthreads();

    if (tid < 144) {
        const int i = tid / CCH, j = tid - CCH * (tid / CCH);
        unsigned long long S3p[6];
#pragma unroll
        for (int k = 0; k < 6; k++) S3p[k] = 0ULL;
        float S2 = 0.0f;
        float s1 = 0.0f;
        const unsigned long long* __restrict__ dx64 =
            (const unsigned long long*)dxsh;                 // 6 u64 per row
        const float4* __restrict__ diT = (const float4*)(dxT + i * TSTRIDE);
        const float4* __restrict__ djT = (const float4*)(dxT + j * TSTRIDE);

// Per step: 3 LDS.128 (as u64 pairs), 2 FMA (cc), 1 mov.b64 pack,
// 6 fma.rn.f32x2 (S3), 2 FMA (S2), 1 FADD (s1).
#define SIG_STEP(tq, di_, dj_) {                                              \
        const unsigned long long* dp = dx64 + (size_t)(tq) * 6;               \
        const ulonglong2 v0 = *(const ulonglong2*)(dp);                       \
        const ulonglong2 v1 = *(const ulonglong2*)(dp + 2);                   \
        const ulonglong2 v2 = *(const ulonglong2*)(dp + 4);                   \
        const float cc = fmaf(fmaf((di_), 1.0f/6.0f, 0.5f * s1), (dj_), S2);  \
        unsigned long long ccp;                                               \
        asm("mov.b64 %0, {%1, %1};" : "=l"(ccp) : "f"(cc));                   \
        asm("fma.rn.f32x2 %0, %1, %2, %0;" : "+l"(S3p[0]) : "l"(ccp), "l"(v0.x)); \
        asm("fma.rn.f32x2 %0, %1, %2, %0;" : "+l"(S3p[1]) : "l"(ccp), "l"(v0.y)); \
        asm("fma.rn.f32x2 %0, %1, %2, %0;" : "+l"(S3p[2]) : "l"(ccp), "l"(v1.x)); \
        asm("fma.rn.f32x2 %0, %1, %2, %0;" : "+l"(S3p[3]) : "l"(ccp), "l"(v1.y)); \
        asm("fma.rn.f32x2 %0, %1, %2, %0;" : "+l"(S3p[4]) : "l"(ccp), "l"(v2.x)); \
        asm("fma.rn.f32x2 %0, %1, %2, %0;" : "+l"(S3p[5]) : "l"(ccp), "l"(v2.y)); \
        S2 = fmaf(fmaf((di_), 0.5f, s1), (dj_), S2);                          \
        s1 += (di_); }

        const int nq = ns >> 2;           // full quads of steps
#pragma unroll 4
        for (int tb = 0; tb < nq; tb++) {
            const float4 di4 = diT[tb];
            const float4 dj4 = djT[tb];
            SIG_STEP(tb * 4 + 0, di4.x, dj4.x);
            SIG_STEP(tb * 4 + 1, di4.y, dj4.y);
            SIG_STEP(tb * 4 + 2, di4.z, dj4.z);
            SIG_STEP(tb * 4 + 3, di4.w, dj4.w);
        }
        for (int t = nq * 4; t < ns; t++) {   // remainder (0 or 3 steps)
            const float di = dxT[i * TSTRIDE + t];
            const float dj = dxT[j * TSTRIDE + t];
            SIG_STEP(t, di, dj);
        }
#undef SIG_STEP

        float* out = &g_part[(size_t)(p * NCHUNK + chunk) * SIGC];
        if (j == 0) out[i] = s1;
        out[L2OFF + tid] = S2;
        // packed pairs are little-endian (lo = even k) -> same layout as floats
        ulonglong2* o2 = (ulonglong2*)(out + L3OFF + tid * 12);
        o2[0] = make_ulonglong2(S3p[0], S3p[1]);
        o2[1] = make_ulonglong2(S3p[2], S3p[3]);
        o2[2] = make_ulonglong2(S3p[4], S3p[5]);
    }
}

// ---------------------------------------------------------------------------
// Kernel 2: per-path combine. grid = 64 (one block per path), block = 512.
// Bulk-stage ALL 8 chunk partials (60 KB) into dynamic smem in one burst,
// then 7 folds entirely from smem, write final signature to g_sig.
// ---------------------------------------------------------------------------
extern __shared__ float dynsh[];

__global__ __launch_bounds__(512) void combine_kernel()
{
    const int tid = threadIdx.x;
    const int p   = blockIdx.x;

    const float4* __restrict__ gsrc =
        (const float4*)&g_part[(size_t)p * NCHUNK * SIGC];
    const int NQ = NCHUNK * SIGQ;   // 3768 float4s
    for (int f = tid; f < NQ; f += 512)
        ((float4*)dynsh)[f] = gsrc[f];
    __syncthreads();

    if (tid < 432) {
        const int t144 = tid / 3;
        const int kg   = tid - 3 * t144;
        const int i    = t144 / CCH;
        const int j    = t144 - CCH * i;

        float4 A3   = *(const float4*)(dynsh + L3OFF + t144 * 12 + kg * 4);
        float  A2ij = dynsh[L2OFF + t144];
        float  a1i  = dynsh[i];

#pragma unroll
        for (int s = 1; s < NCHUNK; s++)
            chen_fold(dynsh + s * SIGC, i, j, t144, kg, A3, A2ij, a1i);

        float* out = &g_sig[(size_t)p * SIGC];
        *(float4*)(out + L3OFF + t144 * 12 + kg * 4) = A3;
        if (kg == 0) {
            out[L2OFF + t144] = A2ij;
            if (j == 0) out[i] = a1i;
        }
    }
}

// ---------------------------------------------------------------------------
// Kernel 3: GEMV + sigmoid. grid = 32 (batch), block = 1024.
// Stage the batch's contiguous sig pair (15 KB) into smem, then warp o
// computes out[b][o] with float4 loads + shuffle reduction.
// ---------------------------------------------------------------------------
__global__ __launch_bounds__(1024) void linear_kernel(const float* __restrict__ lin_w,
                                                      const float* __restrict__ lin_b,
                                                      float* __restrict__ out)
{
    __shared__ __align__(16) float sig[2 * SIGC];   // 15 KB

    const int tid = threadIdx.x;
    const int b   = blockIdx.x;

    const float4* __restrict__ gsig =
        (const float4*)&g_sig[(size_t)(2 * b) * SIGC];
    const int NV = (2 * SIGC) / 4;   // 942
    for (int f = tid; f < NV; f += 1024)
        ((float4*)sig)[f] = gsig[f];
    __syncthreads();

    const int o    = tid >> 5;
    const int lane = tid & 31;
    const float4* __restrict__ s4 = (const float4*)sig;
    const float4* __restrict__ w4 = (const float4*)(lin_w + (size_t)o * 2 * SIGC);

    float ax = 0.0f, ay = 0.0f, az = 0.0f, aw = 0.0f;
    for (int f = lane; f < NV; f += 32) {
        float4 sv = s4[f];
        float4 wv = w4[f];
        ax = fmaf(sv.x, wv.x, ax);
        ay = fmaf(sv.y, wv.y, ay);
        az = fmaf(sv.z, wv.z, az);
        aw = fmaf(sv.w, wv.w, aw);
    }
    float acc = (ax + ay) + (az + aw);
#pragma unroll
    for (int off = 16; off > 0; off >>= 1)
        acc += __shfl_down_sync(0xffffffffu, acc, off);
    if (lane == 0) {
        float z = acc + lin_b[o];
        out[b * 32 + o] = 1.0f / (1.0f + expf(-z));
    }
}

// ---------------------------------------------------------------------------
extern "C" void kernel_launch(void* const* d_in, const int* in_sizes, int n_in,
                              void* d_out, int out_size)
{
    const float* x     = (const float*)d_in[0];  // (32,1024,3)
    const float* aug_w = (const float*)d_in[1];  // (2,8,3)
    // d_in[2] = aug_b : unused (signature is translation-invariant)
    const float* lin_w = (const float*)d_in[3];  // (32, 3768)
    const float* lin_b = (const float*)d_in[4];  // (32,)
    float* out = (float*)d_out;                  // (32,32) float32

    const int dyn_smem = NCHUNK * SIGC * (int)sizeof(float);   // 60,288 B
    cudaFuncSetAttribute(combine_kernel,
                         cudaFuncAttributeMaxDynamicSharedMemorySize, dyn_smem);

    dim3 grid1(NCHUNK, NPATH);
    chunk_kernel<<<grid1, 160>>>(x, aug_w);
    combine_kernel<<<NPATH, 512, dyn_smem>>>();
    linear_kernel<<<32, 1024>>>(lin_w, lin_b, out);
}